// round 11
// baseline (speedup 1.0000x reference)
#include <cuda_runtime.h>
#include <stdint.h>

// SortPooling: B graphs, spans (start,end) per graph, n = end-start in [32,96].
// Select top K=30 rows by feature column 127 (descending, stable ascending-index
// tie-break, matching jax.lax.top_k), copy full 128-float rows to out[b][k][:].

#define BD   128    // feature dim D
#define KK   30     // top-k
#define MAXN 96

// Flag set by probe kernel: 1 if graph_indexes buffer is int64, 0 if int32.
__device__ int g_gidx_is64;

__global__ void probe_gidx_kernel(const void* __restrict__ gidx_raw,
                                  long long n_total, int B)
{
    const long long* g64 = (const long long*)gidx_raw;
    long long s0 = g64[0];
    long long e0 = g64[1];
    long long sl = g64[2LL * (B - 1)];
    long long el = g64[2LL * (B - 1) + 1];
    bool ok64 = (s0 == 0) && (e0 > 0) && (e0 <= 128) &&
                (sl >= 0) && (sl < el) && (el == n_total);
    g_gidx_is64 = ok64 ? 1 : 0;
}

__global__ __launch_bounds__(128, 8)
void sortpool_kernel(const float* __restrict__ feat,
                     const void* __restrict__ gidx_raw,
                     float* __restrict__ out,
                     long long n_total)
{
    const int b   = blockIdx.x;
    const int tid = threadIdx.x;

    long long start, end;
    if (g_gidx_is64) {
        const long long* g = (const long long*)gidx_raw;
        start = g[2LL * b];
        end   = g[2LL * b + 1];
    } else {
        const int* g = (const int*)gidx_raw;
        start = g[2 * b];
        end   = g[2 * b + 1];
    }

    // Defensive clamps: misinterpretation degrades to wrong values, not a crash.
    if (start < 0) start = 0;
    if (start > n_total) start = n_total;
    long long nn = end - start;
    int n = (nn < 0) ? 0 : (nn > MAXN ? MAXN : (int)nn);
    if (start + n > n_total) n = (int)(n_total - start);

    __shared__ float keys[MAXN];
    __shared__ int   src[KK];   // output slot k -> local row index

    // Phase 1: load sort keys (column 127 of each row in the span).
    if (tid < KK) src[tid] = 0;
    if (tid < n) {
        keys[tid] = __ldg(&feat[(start + (long long)tid) * BD + (BD - 1)]);
    }
    __syncthreads();

    // Phase 2: rank selection. rank_j = #{i : key_i > key_j or
    // (key_i == key_j and i < tid)} — descending value, stable index
    // tie-break, exactly jax.lax.top_k ordering. Ranks are a permutation
    // of 0..n-1; since n >= 32 > K, slots 0..K-1 are all filled.
    if (tid < n) {
        const float kj = keys[tid];
        int rank = 0;
        #pragma unroll 4
        for (int i = 0; i < n; ++i) {
            const float ki = keys[i];
            rank += (ki > kj) || (ki == kj && i < tid);
        }
        if (rank < KK) src[rank] = tid;
    }
    __syncthreads();

    // Phase 3: gather K rows of 128 floats -> 30 * 32 = 960 float4 moves,
    // coalesced on both load and store sides, ~8 independent iters/thread.
    float4* __restrict__ dst = (float4*)(out + (size_t)b * (KK * BD));
    const int total = KK * (BD / 4);   // 960
    #pragma unroll 4
    for (int t = tid; t < total; t += 128) {
        const int k = t >> 5;          // which of the K rows
        const int c = t & 31;          // which float4 within the row
        long long row = start + (long long)src[k];
        if (row >= n_total) row = n_total - 1;   // defensive
        dst[t] = __ldg(((const float4*)(feat + row * BD)) + c);
    }
}

extern "C" void kernel_launch(void* const* d_in, const int* in_sizes, int n_in,
                              void* d_out, int out_size)
{
    // Pick inputs by element count: features is huge (~67M), spans are tiny.
    int i_feat = 0, i_gidx = 1;
    if (n_in >= 2 && in_sizes[0] < in_sizes[1]) { i_feat = 1; i_gidx = 0; }

    const float* feat = (const float*)d_in[i_feat];
    const void*  gidx = d_in[i_gidx];
    float*       out  = (float*)d_out;

    const long long n_total = (long long)in_sizes[i_feat] / BD;
    const int       B       = in_sizes[i_gidx] / 2;

    probe_gidx_kernel<<<1, 1>>>(gidx, n_total, B);
    sortpool_kernel<<<B, 128>>>(feat, gidx, out, n_total);
}